// round 12
// baseline (speedup 1.0000x reference)
#include <cuda_runtime.h>

// Fixed shapes
#define B_   16
#define J_   1024
#define L_   4096
#define D4   128          // D/4 float4 lanes
#define NCH  32           // chunks along J
#define CLEN 32           // J per chunk
#define NSG  4            // subgroups per chunk
#define SLEN 8            // J per subgroup
#define EPSV 1e-4f

#define SCAN_BLOCKS   (B_ * (NCH + 1))        // 528
#define GATHER_BLOCKS (B_ * (L_ / 16))        // 4096 (16 rows per block)
#define TOTAL_BLOCKS  (SCAN_BLOCKS + GATHER_BLOCKS)

// Scratch (device globals; flags are epoch-valued -> never need resetting)
__device__ unsigned long long g_ctr;               // replay epoch counter
__device__ unsigned long long g_pub[B_ * NCH];     // hi32=epoch+1, lo32=A bits
__device__ unsigned long long g_done[B_ * NCH];    // ==epoch+1 when chunk final
__device__ unsigned long long g_idxdone[B_];       // ==epoch+1 when idx ready
__device__ float4 g_partialEnd[B_ * NCH * D4];     // chunk end states
__device__ float4 g_smoothed[B_ * J_ * D4];        // FINAL smoothed, 32 MiB
__device__ int    g_idx[B_ * L_];                  // gather indices

// ---------------------------------------------------------------------------
// ONE fused kernel. bid<528: scan/idx blocks (per batch b: 32 chunk blocks
// with decoupled lookback + 1 boundary-scan block). bid>=528: gather blocks
// that wait on flags. Epoch trick makes flags monotone across graph replays.
// ---------------------------------------------------------------------------
__global__ void __launch_bounds__(512, 2)
k_fused(const float4* __restrict__ emb,
        const float*  __restrict__ conf,
        const int*    __restrict__ mask,
        const int*    __restrict__ bnd,
        float4* __restrict__ out) {
    const int bid = blockIdx.x, t = threadIdx.x;

    __shared__ unsigned long long sEp;
    __shared__ float  sa[CLEN], sb[CLEN], sSeg[CLEN], sGA[NSG], sPF[CLEN];
    __shared__ float  sChunkA;
    __shared__ float  sP[32];
    __shared__ int    swsum[16];
    __shared__ float4 sVec[NSG][D4];

    if (t == 0) sEp = atomicAdd(&g_ctr, 1ULL) / TOTAL_BLOCKS;
    __syncthreads();
    const unsigned ep1 = (unsigned)(sEp + 1ULL);       // this replay's flag value
    const unsigned long long ep1ll = (unsigned long long)ep1;

    // =================== GATHER BLOCKS ===================
    if (bid >= SCAN_BLOCKS) {
        const int gid = bid - SCAN_BLOCKS;
        const int b = gid >> 8;                        // 256 tiles per batch
        const int l0 = (gid & 255) * 16;
        const int w = t >> 5, lane = t & 31;

        // wait for this batch's idx array (broadcast poll)
        {
            volatile unsigned long long* f = &g_idxdone[b];
            while (*f != ep1ll) __nanosleep(200);
        }
        __threadfence();

        const int l = l0 + w;                          // one row per warp
        const int j = g_idx[b * L_ + l];

        // wait for the smoothed chunk holding j
        {
            volatile unsigned long long* df = &g_done[b * NCH + (j >> 5)];
            while (*df != ep1ll) __nanosleep(100);
        }
        __threadfence();

        const float4* __restrict__ sp = g_smoothed + ((size_t)b * J_ + j) * D4;
        float4* __restrict__ op = out + ((size_t)b * L_ + l) * D4;
        float4 pv[4];
        #pragma unroll
        for (int k = 0; k < 4; k++) pv[k] = sp[k * 32 + lane];
        #pragma unroll
        for (int k = 0; k < 4; k++) __stcs(op + k * 32 + lane, pv[k]);
        return;
    }

    // =================== SCAN / IDX BLOCKS ===================
    const int b = bid / (NCH + 1), c = bid % (NCH + 1);

    if (c == NCH) {
        // ---- boundary scan -> gather idx: 512 threads, 8 elems/thread ----
        const int lane = t & 31, w = t >> 5;           // 16 warps
        const int* p = bnd + b * L_ + t * 8;
        int v[8];
        int s = 0;
        #pragma unroll
        for (int i = 0; i < 8; i++) { v[i] = p[i]; s += (v[i] != 0); }

        int incl = s;
        #pragma unroll
        for (int off = 1; off < 32; off <<= 1) {
            int u = __shfl_up_sync(0xFFFFFFFFu, incl, off);
            if (lane >= off) incl += u;
        }
        if (lane == 31) swsum[w] = incl;
        __syncthreads();
        if (t < 16) {
            int x = swsum[t];
            #pragma unroll
            for (int off = 1; off < 16; off <<= 1) {
                int u = __shfl_up_sync(0x0000FFFFu, x, off);
                if (t >= off) x += u;
            }
            swsum[t] = x;
        }
        __syncthreads();

        int run = incl - s + (w ? swsum[w - 1] : 0);
        int* op = g_idx + b * L_ + t * 8;
        #pragma unroll
        for (int i = 0; i < 8; i++) {
            run += (v[i] != 0);
            int id = run - 1;
            id = id < 0 ? 0 : (id > (J_ - 1) ? (J_ - 1) : id);
            op[i] = id;
        }
        __threadfence();
        __syncthreads();
        if (t == 0) atomicExch(&g_idxdone[b], ep1ll);
        return;
    }

    // ---- EMA chunk scan with decoupled lookback ----
    const int g = t >> 7, d4 = t & 127;

    // 1) prefetch emb (streaming)
    const int jb = g * SLEN;
    const size_t base = ((size_t)b * J_ + (size_t)c * CLEN + jb) * D4 + d4;
    const float4* ep = emb + base;
    float4 e[SLEN];
    #pragma unroll
    for (int i = 0; i < SLEN; i++) e[i] = __ldcs(ep + (size_t)i * D4);

    // 2) warp-0 prologue
    if (t < CLEN) {
        const int j = c * CLEN + t;
        float p = conf[b * J_ + j];
        p = fminf(fmaxf(p, EPSV), 1.0f - EPSV);
        const bool m = mask[b * J_ + j] != 0;
        const float a = m ? (1.0f - p) : 1.0f;
        sa[t] = a;
        sb[t] = m ? p : 0.0f;

        float pf = a;
        #pragma unroll
        for (int off = 1; off < 32; off <<= 1) {
            float v = __shfl_up_sync(0xFFFFFFFFu, pf, off);
            if (t >= off) pf *= v;
        }
        sPF[t] = pf;
        if (t == 31) sChunkA = pf;

        float ps = a;
        #pragma unroll
        for (int off = 1; off < SLEN; off <<= 1) {
            float v = __shfl_up_sync(0xFFFFFFFFu, ps, off, SLEN);
            if ((t & (SLEN - 1)) >= off) ps *= v;
        }
        sSeg[t] = ps;
        if ((t & (SLEN - 1)) == SLEN - 1) sGA[t >> 3] = ps;
    }
    __syncthreads();

    // 3) subgroup zero-start scan
    float4 prev = make_float4(0.f, 0.f, 0.f, 0.f);
    #pragma unroll
    for (int i = 0; i < SLEN; i++) {
        const float a = sa[jb + i], bb = sb[jb + i];
        prev.x = fmaf(a, prev.x, bb * e[i].x);
        prev.y = fmaf(a, prev.y, bb * e[i].y);
        prev.z = fmaf(a, prev.z, bb * e[i].z);
        prev.w = fmaf(a, prev.w, bb * e[i].w);
        e[i] = prev;
    }
    sVec[g][d4] = prev;
    __syncthreads();

    // 4) intra-block carry -> e[] = chunk-local scan
    {
        float4 cg = make_float4(0.f, 0.f, 0.f, 0.f);
        if (g >= 1) cg = sVec[0][d4];
        if (g >= 2) {
            const float4 e1 = sVec[1][d4];
            const float A1 = sGA[1];
            cg.x = fmaf(A1, cg.x, e1.x);
            cg.y = fmaf(A1, cg.y, e1.y);
            cg.z = fmaf(A1, cg.z, e1.z);
            cg.w = fmaf(A1, cg.w, e1.w);
        }
        if (g >= 3) {
            const float4 e2 = sVec[2][d4];
            const float A2 = sGA[2];
            cg.x = fmaf(A2, cg.x, e2.x);
            cg.y = fmaf(A2, cg.y, e2.y);
            cg.z = fmaf(A2, cg.z, e2.z);
            cg.w = fmaf(A2, cg.w, e2.w);
        }
        #pragma unroll
        for (int i = 0; i < SLEN; i++) {
            const float w = sSeg[jb + i];
            e[i].x = fmaf(w, cg.x, e[i].x);
            e[i].y = fmaf(w, cg.y, e[i].y);
            e[i].z = fmaf(w, cg.z, e[i].z);
            e[i].w = fmaf(w, cg.w, e[i].w);
        }
    }

    // 5) publish chunk end + A
    if (g == NSG - 1)
        g_partialEnd[(b * NCH + c) * D4 + d4] = e[SLEN - 1];
    __threadfence();
    __syncthreads();
    if (t == 0) {
        unsigned long long v =
            ((unsigned long long)ep1 << 32) |
            (unsigned long long)__float_as_uint(sChunkA);
        atomicExch(&g_pub[b * NCH + c], v);
    }

    // 6) lookback: combine ALL predecessor partials
    float4 carry = make_float4(0.f, 0.f, 0.f, 0.f);
    if (c > 0) {
        if (t < 32) {
            float Ak = 1.0f;
            if (t < c) {
                volatile unsigned long long* vf = &g_pub[b * NCH + t];
                unsigned long long v = *vf;
                while ((unsigned)(v >> 32) != ep1) { __nanosleep(40); v = *vf; }
                Ak = __uint_as_float((unsigned)(v & 0xFFFFFFFFu));
            }
            float s = Ak;
            #pragma unroll
            for (int off = 1; off < 32; off <<= 1) {
                float v2 = __shfl_down_sync(0xFFFFFFFFu, s, off);
                if (t + off < c) s *= v2;
            }
            float P = __shfl_down_sync(0xFFFFFFFFu, s, 1);
            if (t + 1 >= c) P = 1.0f;
            sP[t] = P;
        }
        __syncthreads();

        float4 acc = make_float4(0.f, 0.f, 0.f, 0.f);
        #pragma unroll 2
        for (int k = g; k < c; k += NSG) {
            const float4 ev = __ldcg(&g_partialEnd[(b * NCH + k) * D4 + d4]);
            const float Pk = sP[k];
            acc.x = fmaf(Pk, ev.x, acc.x);
            acc.y = fmaf(Pk, ev.y, acc.y);
            acc.z = fmaf(Pk, ev.z, acc.z);
            acc.w = fmaf(Pk, ev.w, acc.w);
        }
        sVec[g][d4] = acc;
        __syncthreads();
        carry = sVec[0][d4];
        #pragma unroll
        for (int g2 = 1; g2 < NSG; g2++) {
            const float4 a2 = sVec[g2][d4];
            carry.x += a2.x; carry.y += a2.y; carry.z += a2.z; carry.w += a2.w;
        }
    }

    // 7) final smoothed + done flag
    float4* sp = g_smoothed + base;
    #pragma unroll
    for (int i = 0; i < SLEN; i++) {
        const float w = sPF[jb + i];
        float4 r;
        r.x = fmaf(w, carry.x, e[i].x);
        r.y = fmaf(w, carry.y, e[i].y);
        r.z = fmaf(w, carry.z, e[i].z);
        r.w = fmaf(w, carry.w, e[i].w);
        sp[(size_t)i * D4] = r;
    }
    __threadfence();
    __syncthreads();
    if (t == 0) atomicExch(&g_done[b * NCH + c], ep1ll);
}

// ---------------------------------------------------------------------------
extern "C" void kernel_launch(void* const* d_in, const int* in_sizes, int n_in,
                              void* d_out, int out_size) {
    const float4* emb  = (const float4*)d_in[0];  // (16,1024,512) f32
    const float*  conf = (const float*)d_in[1];   // (16,1024) f32
    const int*    msk  = (const int*)d_in[2];     // (16,1024) bool->int32
    const int*    bnd  = (const int*)d_in[3];     // (16,4096) bool->int32
    float4* out = (float4*)d_out;                 // (16,4096,512) f32

    k_fused<<<TOTAL_BLOCKS, 512>>>(emb, conf, msk, bnd, out);
}

// round 13
// speedup vs baseline: 1.3571x; 1.3571x over previous
#include <cuda_runtime.h>

// Fixed shapes
#define B_   16
#define J_   1024
#define L_   4096
#define D4   128          // D/4 float4 lanes
#define NCH  32           // chunks along J
#define CLEN 32           // J per chunk
#define NSG  4            // subgroups per chunk (inside block)
#define SLEN 8            // J per subgroup
#define EPSV 1e-4f

// Scratch (device globals)
__device__ float  g_partialA[B_ * NCH];          // per-chunk total decay product
__device__ float  g_cumA[B_ * J_];               // within-chunk inclusive prod(a)
__device__ float4 g_partialEnd[B_ * NCH * D4];   // per-chunk end state (prev=0)
__device__ float4 g_carry[B_ * NCH * D4];        // state entering each chunk
__device__ float4 g_smoothed[B_ * J_ * D4];      // chunk-exact scan, 32 MiB
__device__ int    g_idx[B_ * L_];                // gather indices

// ---------------------------------------------------------------------------
// Kernel 1: grid ((NCH+1), B), 512 threads.
//  blocks c<NCH : per-chunk exact EMA from prev=0 (4 subgroups x 8 steps)
//  blocks c==NCH: boundary-mask scan -> gather indices for batch b
// emb loads via __ldcg: emb should persist in L2 across graph replays
// (out stores are write-through, so L2 has room for emb + smoothed).
// ---------------------------------------------------------------------------
__global__ void __launch_bounds__(512, 2)
k_partial(const float4* __restrict__ emb,
          const float*  __restrict__ conf,
          const int*    __restrict__ mask,
          const int*    __restrict__ bnd) {
    const int c = blockIdx.x, b = blockIdx.y, t = threadIdx.x;

    if (c == NCH) {
        // ---- boundary scan -> gather idx: 512 threads, 8 elems/thread ----
        const int lane = t & 31, w = t >> 5;    // 16 warps
        __shared__ int wsum[16];

        const int* p = bnd + b * L_ + t * 8;
        int v[8];
        int s = 0;
        #pragma unroll
        for (int i = 0; i < 8; i++) { v[i] = p[i]; s += (v[i] != 0); }

        int incl = s;
        #pragma unroll
        for (int off = 1; off < 32; off <<= 1) {
            int u = __shfl_up_sync(0xFFFFFFFFu, incl, off);
            if (lane >= off) incl += u;
        }
        if (lane == 31) wsum[w] = incl;
        __syncthreads();
        if (t < 16) {
            int x = wsum[t];
            #pragma unroll
            for (int off = 1; off < 16; off <<= 1) {
                int u = __shfl_up_sync(0x0000FFFFu, x, off);
                if (t >= off) x += u;
            }
            wsum[t] = x;
        }
        __syncthreads();

        int run = incl - s + (w ? wsum[w - 1] : 0);   // exclusive prefix
        int* op = g_idx + b * L_ + t * 8;
        #pragma unroll
        for (int i = 0; i < 8; i++) {
            run += (v[i] != 0);
            int id = run - 1;
            id = id < 0 ? 0 : (id > (J_ - 1) ? (J_ - 1) : id);
            op[i] = id;
        }
        return;
    }

    // ---- EMA chunk scan ----
    const int g = t >> 7, d4 = t & 127;

    __shared__ float  sa[CLEN], sb[CLEN], sSeg[CLEN], sGA[NSG];
    __shared__ float4 sEnd[NSG][D4];

    // 1) issue the main loads FIRST (L2-persistent policy)
    const int jb = g * SLEN;
    const size_t base = ((size_t)b * J_ + (size_t)c * CLEN + jb) * D4 + d4;
    const float4* ep = emb + base;

    float4 e[SLEN];
    #pragma unroll
    for (int i = 0; i < SLEN; i++) e[i] = __ldcg(ep + (size_t)i * D4);

    // 2) warp-0 prologue runs while the loads are in flight
    if (t < CLEN) {
        const int j = c * CLEN + t;
        float p = conf[b * J_ + j];
        p = fminf(fmaxf(p, EPSV), 1.0f - EPSV);
        const bool m = mask[b * J_ + j] != 0;
        const float a = m ? (1.0f - p) : 1.0f;
        sa[t] = a;
        sb[t] = m ? p : 0.0f;

        // full inclusive product scan (width 32) -> cumA / chunk A
        float pf = a;
        #pragma unroll
        for (int off = 1; off < 32; off <<= 1) {
            float v = __shfl_up_sync(0xFFFFFFFFu, pf, off);
            if (t >= off) pf *= v;
        }
        g_cumA[b * J_ + j] = pf;
        if (t == 31) g_partialA[b * NCH + c] = pf;

        // segmented inclusive product scan (width 8)
        float ps = a;
        #pragma unroll
        for (int off = 1; off < SLEN; off <<= 1) {
            float v = __shfl_up_sync(0xFFFFFFFFu, ps, off, SLEN);
            if ((t & (SLEN - 1)) >= off) ps *= v;
        }
        sSeg[t] = ps;
        if ((t & (SLEN - 1)) == SLEN - 1) sGA[t >> 3] = ps;
    }
    __syncthreads();

    // 3) subgroup zero-start partial scan consuming the prefetched e[]
    float4 prev = make_float4(0.f, 0.f, 0.f, 0.f);
    #pragma unroll
    for (int i = 0; i < SLEN; i++) {
        const float a = sa[jb + i], bb = sb[jb + i];
        prev.x = fmaf(a, prev.x, bb * e[i].x);
        prev.y = fmaf(a, prev.y, bb * e[i].y);
        prev.z = fmaf(a, prev.z, bb * e[i].z);
        prev.w = fmaf(a, prev.w, bb * e[i].w);
        e[i] = prev;                              // e[i] = p[i]
    }
    sEnd[g][d4] = prev;
    __syncthreads();

    // entering carry for this subgroup (<=3 FMAs from shared ends)
    float4 cg = make_float4(0.f, 0.f, 0.f, 0.f);
    if (g >= 1) cg = sEnd[0][d4];
    if (g >= 2) {
        const float4 e1 = sEnd[1][d4];
        const float A1 = sGA[1];
        cg.x = fmaf(A1, cg.x, e1.x);
        cg.y = fmaf(A1, cg.y, e1.y);
        cg.z = fmaf(A1, cg.z, e1.z);
        cg.w = fmaf(A1, cg.w, e1.w);
    }
    if (g >= 3) {
        const float4 e2 = sEnd[2][d4];
        const float A2 = sGA[2];
        cg.x = fmaf(A2, cg.x, e2.x);
        cg.y = fmaf(A2, cg.y, e2.y);
        cg.z = fmaf(A2, cg.z, e2.z);
        cg.w = fmaf(A2, cg.w, e2.w);
    }

    // corrected values: s[j] = p[j] + seg(j) * cg ; store coalesced
    float4* sp = g_smoothed + base;
    float4 last;
    #pragma unroll
    for (int i = 0; i < SLEN; i++) {
        const float w = sSeg[jb + i];
        float4 r;
        r.x = fmaf(w, cg.x, e[i].x);
        r.y = fmaf(w, cg.y, e[i].y);
        r.z = fmaf(w, cg.z, e[i].z);
        r.w = fmaf(w, cg.w, e[i].w);
        sp[(size_t)i * D4] = r;
        last = r;
    }
    if (g == NSG - 1)
        g_partialEnd[(b * NCH + c) * D4 + d4] = last;
}

// ---------------------------------------------------------------------------
// Kernel 2: carry combine only. grid (B), 128 threads, register preload.
// ---------------------------------------------------------------------------
__global__ void k_carry() {
    const int b = blockIdx.x, t = threadIdx.x;
    __shared__ float sA[NCH];
    if (t < NCH) sA[t] = g_partialA[b * NCH + t];

    float4 e[NCH];
    #pragma unroll
    for (int c = 0; c < NCH; c++)
        e[c] = g_partialEnd[(b * NCH + c) * D4 + t];
    __syncthreads();

    float4 s = make_float4(0.f, 0.f, 0.f, 0.f);
    g_carry[(b * NCH + 0) * D4 + t] = s;
    #pragma unroll
    for (int c = 1; c < NCH; c++) {
        const float A = sA[c - 1];
        s.x = fmaf(A, s.x, e[c - 1].x);
        s.y = fmaf(A, s.y, e[c - 1].y);
        s.z = fmaf(A, s.z, e[c - 1].z);
        s.w = fmaf(A, s.w, e[c - 1].w);
        g_carry[(b * NCH + c) * D4 + t] = s;
    }
}

// ---------------------------------------------------------------------------
// Kernel 3: fused correction + gather, one warp per (b,l) row.
// out[b,l,d] = smoothed[b,j,d] + cumA[b,j] * carry[b, j>>5, d], j = idx[b,l]
// out stores are WRITE-THROUGH (__stwt): they never allocate in L2, so
// emb + smoothed stay L2-resident across graph replays.
// ---------------------------------------------------------------------------
__global__ void k_gather(float4* __restrict__ out) {
    const unsigned int wg = (blockIdx.x * blockDim.x + threadIdx.x) >> 5;
    const int lane = threadIdx.x & 31;
    const int l = wg & (L_ - 1);
    const int b = wg >> 12;

    const int j = g_idx[b * L_ + l];
    const float w = g_cumA[b * J_ + j];
    const int c = j >> 5;
    const float4* __restrict__ sp = g_smoothed + ((size_t)b * J_ + j) * D4;
    const float4* __restrict__ cp = g_carry + (b * NCH + c) * D4;
    float4* __restrict__ op = out + ((size_t)b * L_ + l) * D4;

    float4 pv[4], cv[4];
    #pragma unroll
    for (int k = 0; k < 4; k++) {
        const int d = k * 32 + lane;
        pv[k] = sp[d];
        cv[k] = cp[d];
    }
    #pragma unroll
    for (int k = 0; k < 4; k++) {
        const int d = k * 32 + lane;
        float4 r;
        r.x = fmaf(w, cv[k].x, pv[k].x);
        r.y = fmaf(w, cv[k].y, pv[k].y);
        r.z = fmaf(w, cv[k].z, pv[k].z);
        r.w = fmaf(w, cv[k].w, pv[k].w);
        __stwt(op + d, r);
    }
}

// ---------------------------------------------------------------------------
extern "C" void kernel_launch(void* const* d_in, const int* in_sizes, int n_in,
                              void* d_out, int out_size) {
    const float4* emb  = (const float4*)d_in[0];  // (16,1024,512) f32
    const float*  conf = (const float*)d_in[1];   // (16,1024) f32
    const int*    msk  = (const int*)d_in[2];     // (16,1024) bool->int32
    const int*    bnd  = (const int*)d_in[3];     // (16,4096) bool->int32
    float4* out = (float4*)d_out;                 // (16,4096,512) f32

    k_partial<<<dim3(NCH + 1, B_), 512>>>(emb, conf, msk, bnd);
    k_carry<<<B_, D4>>>();
    k_gather<<<(B_ * L_ * 32) / 256, 256>>>(out);
}

// round 15
// speedup vs baseline: 1.6226x; 1.1956x over previous
#include <cuda_runtime.h>

// Fixed shapes
#define B_   16
#define J_   1024
#define L_   4096
#define D4   128          // D/4 float4 lanes
#define NCH  32           // chunks along J
#define CLEN 32           // J per chunk
#define NSG  4            // subgroups per chunk (inside block)
#define SLEN 8            // J per subgroup
#define EPSV 1e-4f

// Scratch (device globals)
__device__ float  g_partialA[B_ * NCH];          // per-chunk total decay product
__device__ float  g_cumA[B_ * J_];               // within-chunk inclusive prod(a)
__device__ float4 g_partialEnd[B_ * NCH * D4];   // per-chunk end state (prev=0)
__device__ float4 g_carry[B_ * NCH * D4];        // state entering each chunk
__device__ float4 g_smoothed[B_ * J_ * D4];      // chunk-exact scan, 32 MiB
__device__ int    g_idx[B_ * L_];                // gather indices

// ---------------------------------------------------------------------------
// Kernel 1: grid ((NCH+1), B), 512 threads.
//  blocks c<NCH : per-chunk exact EMA from prev=0 (4 subgroups x 8 steps)
//  blocks c==NCH: boundary-mask scan -> gather indices for batch b
// ---------------------------------------------------------------------------
__global__ void __launch_bounds__(512, 2)
k_partial(const float4* __restrict__ emb,
          const float*  __restrict__ conf,
          const int*    __restrict__ mask,
          const int*    __restrict__ bnd) {
    const int c = blockIdx.x, b = blockIdx.y, t = threadIdx.x;

    if (c == NCH) {
        // ---- boundary scan -> gather idx: 512 threads, 8 elems/thread ----
        const int lane = t & 31, w = t >> 5;    // 16 warps
        __shared__ int wsum[16];

        const int* p = bnd + b * L_ + t * 8;
        int v[8];
        int s = 0;
        #pragma unroll
        for (int i = 0; i < 8; i++) { v[i] = p[i]; s += (v[i] != 0); }

        int incl = s;
        #pragma unroll
        for (int off = 1; off < 32; off <<= 1) {
            int u = __shfl_up_sync(0xFFFFFFFFu, incl, off);
            if (lane >= off) incl += u;
        }
        if (lane == 31) wsum[w] = incl;
        __syncthreads();
        if (t < 16) {
            int x = wsum[t];
            #pragma unroll
            for (int off = 1; off < 16; off <<= 1) {
                int u = __shfl_up_sync(0x0000FFFFu, x, off);
                if (t >= off) x += u;
            }
            wsum[t] = x;
        }
        __syncthreads();

        int run = incl - s + (w ? wsum[w - 1] : 0);   // exclusive prefix
        int* op = g_idx + b * L_ + t * 8;
        #pragma unroll
        for (int i = 0; i < 8; i++) {
            run += (v[i] != 0);
            int id = run - 1;
            id = id < 0 ? 0 : (id > (J_ - 1) ? (J_ - 1) : id);
            op[i] = id;
        }
        return;
    }

    // ---- EMA chunk scan ----
    const int g = t >> 7, d4 = t & 127;

    __shared__ float  sa[CLEN], sb[CLEN], sSeg[CLEN], sGA[NSG];
    __shared__ float4 sEnd[NSG][D4];

    // 1) issue the main loads FIRST (independent of everything below)
    const int jb = g * SLEN;
    const size_t base = ((size_t)b * J_ + (size_t)c * CLEN + jb) * D4 + d4;
    const float4* ep = emb + base;

    float4 e[SLEN];
    #pragma unroll
    for (int i = 0; i < SLEN; i++) e[i] = __ldcs(ep + (size_t)i * D4);

    // 2) warp-0 prologue runs while the loads are in flight
    if (t < CLEN) {
        const int j = c * CLEN + t;
        float p = conf[b * J_ + j];
        p = fminf(fmaxf(p, EPSV), 1.0f - EPSV);
        const bool m = mask[b * J_ + j] != 0;
        const float a = m ? (1.0f - p) : 1.0f;
        sa[t] = a;
        sb[t] = m ? p : 0.0f;

        // full inclusive product scan (width 32) -> cumA / chunk A
        float pf = a;
        #pragma unroll
        for (int off = 1; off < 32; off <<= 1) {
            float v = __shfl_up_sync(0xFFFFFFFFu, pf, off);
            if (t >= off) pf *= v;
        }
        g_cumA[b * J_ + j] = pf;
        if (t == 31) g_partialA[b * NCH + c] = pf;

        // segmented inclusive product scan (width 8)
        float ps = a;
        #pragma unroll
        for (int off = 1; off < SLEN; off <<= 1) {
            float v = __shfl_up_sync(0xFFFFFFFFu, ps, off, SLEN);
            if ((t & (SLEN - 1)) >= off) ps *= v;
        }
        sSeg[t] = ps;
        if ((t & (SLEN - 1)) == SLEN - 1) sGA[t >> 3] = ps;
    }
    __syncthreads();

    // 3) subgroup zero-start partial scan consuming the prefetched e[]
    float4 prev = make_float4(0.f, 0.f, 0.f, 0.f);
    #pragma unroll
    for (int i = 0; i < SLEN; i++) {
        const float a = sa[jb + i], bb = sb[jb + i];
        prev.x = fmaf(a, prev.x, bb * e[i].x);
        prev.y = fmaf(a, prev.y, bb * e[i].y);
        prev.z = fmaf(a, prev.z, bb * e[i].z);
        prev.w = fmaf(a, prev.w, bb * e[i].w);
        e[i] = prev;                              // e[i] = p[i]
    }
    sEnd[g][d4] = prev;
    __syncthreads();

    // entering carry for this subgroup (<=3 FMAs from shared ends)
    float4 cg = make_float4(0.f, 0.f, 0.f, 0.f);
    if (g >= 1) cg = sEnd[0][d4];
    if (g >= 2) {
        const float4 e1 = sEnd[1][d4];
        const float A1 = sGA[1];
        cg.x = fmaf(A1, cg.x, e1.x);
        cg.y = fmaf(A1, cg.y, e1.y);
        cg.z = fmaf(A1, cg.z, e1.z);
        cg.w = fmaf(A1, cg.w, e1.w);
    }
    if (g >= 3) {
        const float4 e2 = sEnd[2][d4];
        const float A2 = sGA[2];
        cg.x = fmaf(A2, cg.x, e2.x);
        cg.y = fmaf(A2, cg.y, e2.y);
        cg.z = fmaf(A2, cg.z, e2.z);
        cg.w = fmaf(A2, cg.w, e2.w);
    }

    // corrected values: s[j] = p[j] + seg(j) * cg ; store coalesced
    float4* sp = g_smoothed + base;
    float4 last;
    #pragma unroll
    for (int i = 0; i < SLEN; i++) {
        const float w = sSeg[jb + i];
        float4 r;
        r.x = fmaf(w, cg.x, e[i].x);
        r.y = fmaf(w, cg.y, e[i].y);
        r.z = fmaf(w, cg.z, e[i].z);
        r.w = fmaf(w, cg.w, e[i].w);
        sp[(size_t)i * D4] = r;
        last = r;
    }
    if (g == NSG - 1)
        g_partialEnd[(b * NCH + c) * D4 + d4] = last;
}

// ---------------------------------------------------------------------------
// Kernel 2: carry combine only. grid (B), 128 threads, register preload.
// ---------------------------------------------------------------------------
__global__ void k_carry() {
    const int b = blockIdx.x, t = threadIdx.x;
    __shared__ float sA[NCH];
    if (t < NCH) sA[t] = g_partialA[b * NCH + t];

    float4 e[NCH];
    #pragma unroll
    for (int c = 0; c < NCH; c++)
        e[c] = g_partialEnd[(b * NCH + c) * D4 + t];
    __syncthreads();

    float4 s = make_float4(0.f, 0.f, 0.f, 0.f);
    g_carry[(b * NCH + 0) * D4 + t] = s;
    #pragma unroll
    for (int c = 1; c < NCH; c++) {
        const float A = sA[c - 1];
        s.x = fmaf(A, s.x, e[c - 1].x);
        s.y = fmaf(A, s.y, e[c - 1].y);
        s.z = fmaf(A, s.z, e[c - 1].z);
        s.w = fmaf(A, s.w, e[c - 1].w);
        g_carry[(b * NCH + c) * D4 + t] = s;
    }
}

// ---------------------------------------------------------------------------
// Kernel 3: fused correction + gather, TWO rows per warp for higher MLP.
// out[b,l,d] = smoothed[b,j,d] + cumA[b,j] * carry[b, j>>5, d], j = idx[b,l]
// 16 independent loads + 8 streaming stores in flight per warp.
// ---------------------------------------------------------------------------
__global__ void k_gather(float4* __restrict__ out) {
    const unsigned int wg = (blockIdx.x * blockDim.x + threadIdx.x) >> 5;
    const int lane = threadIdx.x & 31;
    const int lp = (wg << 1) & (L_ - 1);         // first of 2 rows
    const int b = wg >> 11;                      // 2048 warps per batch

    const int j0 = g_idx[b * L_ + lp];
    const int j1 = g_idx[b * L_ + lp + 1];
    const float w0 = g_cumA[b * J_ + j0];
    const float w1 = g_cumA[b * J_ + j1];
    const float4* __restrict__ sp0 = g_smoothed + ((size_t)b * J_ + j0) * D4;
    const float4* __restrict__ sp1 = g_smoothed + ((size_t)b * J_ + j1) * D4;
    const float4* __restrict__ cp0 = g_carry + (b * NCH + (j0 >> 5)) * D4;
    const float4* __restrict__ cp1 = g_carry + (b * NCH + (j1 >> 5)) * D4;
    float4* __restrict__ op0 = out + ((size_t)b * L_ + lp) * D4;
    float4* __restrict__ op1 = out + ((size_t)b * L_ + lp + 1) * D4;

    float4 pv0[4], cv0[4], pv1[4], cv1[4];
    #pragma unroll
    for (int k = 0; k < 4; k++) {
        const int d = k * 32 + lane;
        pv0[k] = sp0[d];
        pv1[k] = sp1[d];
        cv0[k] = cp0[d];
        cv1[k] = cp1[d];
    }
    #pragma unroll
    for (int k = 0; k < 4; k++) {
        const int d = k * 32 + lane;
        float4 r0, r1;
        r0.x = fmaf(w0, cv0[k].x, pv0[k].x);
        r0.y = fmaf(w0, cv0[k].y, pv0[k].y);
        r0.z = fmaf(w0, cv0[k].z, pv0[k].z);
        r0.w = fmaf(w0, cv0[k].w, pv0[k].w);
        r1.x = fmaf(w1, cv1[k].x, pv1[k].x);
        r1.y = fmaf(w1, cv1[k].y, pv1[k].y);
        r1.z = fmaf(w1, cv1[k].z, pv1[k].z);
        r1.w = fmaf(w1, cv1[k].w, pv1[k].w);
        __stcs(op0 + d, r0);
        __stcs(op1 + d, r1);
    }
}

// ---------------------------------------------------------------------------
extern "C" void kernel_launch(void* const* d_in, const int* in_sizes, int n_in,
                              void* d_out, int out_size) {
    const float4* emb  = (const float4*)d_in[0];  // (16,1024,512) f32
    const float*  conf = (const float*)d_in[1];   // (16,1024) f32
    const int*    msk  = (const int*)d_in[2];     // (16,1024) bool->int32
    const int*    bnd  = (const int*)d_in[3];     // (16,4096) bool->int32
    float4* out = (float4*)d_out;                 // (16,4096,512) f32

    k_partial<<<dim3(NCH + 1, B_), 512>>>(emb, conf, msk, bnd);
    k_carry<<<B_, D4>>>();
    // 2 rows per warp: 16*4096/2 warps = 32768 warps = 4096 blocks x 256
    k_gather<<<(B_ * L_ * 16) / 256, 256>>>(out);
}